// round 5
// baseline (speedup 1.0000x reference)
#include <cuda_runtime.h>
#include <cuda_bf16.h>
#include <math.h>

// Problem constants (fixed shapes per reference)
#define DIMV      1024
#define HIDDENV   2048
#define NEXP      8
#define NTOK      2048
#define TOPKV     2

// GEMM tiling
#define TM 128
#define TN 128
#define TKc 8

// ---------------- device scratch (no allocations allowed) ----------------
__device__ int   g_topk_idx[NTOK * TOPKV];
__device__ float g_topk_w  [NTOK * TOPKV];
__device__ int   g_counts  [NEXP];
__device__ int   g_offsets [NEXP];
__device__ int   g_cursors [NEXP];
__device__ int   g_slot_token[NTOK * TOPKV];
__device__ float g_slot_w    [NTOK * TOPKV];
// relu^2 activations, one row per (token,expert) slot: 4096 x 2048 f32 = 32 MB
__device__ float g_hsq[(size_t)NTOK * TOPKV * HIDDENV];

// ---------------- zero output ----------------
__global__ void zero_kernel(float* __restrict__ out, int n) {
    int i = blockIdx.x * blockDim.x + threadIdx.x;
    if (i < n) out[i] = 0.0f;
}

// ---------------- router: logits -> softmax -> top2 -> renorm ----------------
__global__ __launch_bounds__(128)
void router_kernel(const float* __restrict__ x, const float* __restrict__ Wr) {
    __shared__ float sWr[NEXP * DIMV];   // 32 KB
    int tid = threadIdx.x;
    for (int i = tid; i < NEXP * DIMV; i += 128) sWr[i] = Wr[i];
    __syncthreads();

    int warp = tid >> 5, lane = tid & 31;
    int t = blockIdx.x * 4 + warp;
    const float* xr = x + (size_t)t * DIMV;

    float xreg[DIMV / 32];
#pragma unroll
    for (int i = 0; i < DIMV / 32; i++) xreg[i] = xr[i * 32 + lane];

    float logits[NEXP];
#pragma unroll
    for (int e = 0; e < NEXP; e++) {
        float s = 0.f;
#pragma unroll
        for (int i = 0; i < DIMV / 32; i++) s += xreg[i] * sWr[e * DIMV + i * 32 + lane];
#pragma unroll
        for (int o = 16; o; o >>= 1) s += __shfl_xor_sync(0xffffffffu, s, o);
        logits[e] = s;
    }

    if (lane == 0) {
        float mx = logits[0];
#pragma unroll
        for (int e = 1; e < NEXP; e++) mx = fmaxf(mx, logits[e]);
        float p[NEXP], sum = 0.f;
#pragma unroll
        for (int e = 0; e < NEXP; e++) { p[e] = expf(logits[e] - mx); sum += p[e]; }
        float inv = 1.f / sum;
#pragma unroll
        for (int e = 0; e < NEXP; e++) p[e] *= inv;

        // top-2 (strict > keeps first index on ties, matching jax top_k)
        int i1 = -1, i2 = -1; float p1 = -1.f, p2 = -1.f;
#pragma unroll
        for (int e = 0; e < NEXP; e++) {
            if (p[e] > p1) { p2 = p1; i2 = i1; p1 = p[e]; i1 = e; }
            else if (p[e] > p2) { p2 = p[e]; i2 = e; }
        }
        float denom = p1 + p2 + 1e-8f;
        g_topk_idx[t * 2 + 0] = i1; g_topk_idx[t * 2 + 1] = i2;
        g_topk_w  [t * 2 + 0] = p1 / denom;
        g_topk_w  [t * 2 + 1] = p2 / denom;
    }
}

// ---------------- build per-expert compacted slot lists ----------------
__global__ __launch_bounds__(256)
void build_kernel() {
    __shared__ int sc[NEXP];
    int tid = threadIdx.x;
    if (tid < NEXP) sc[tid] = 0;
    __syncthreads();
    for (int t = tid; t < NTOK; t += 256) {
        atomicAdd(&sc[g_topk_idx[t * 2 + 0]], 1);
        atomicAdd(&sc[g_topk_idx[t * 2 + 1]], 1);
    }
    __syncthreads();
    if (tid == 0) {
        int off = 0;
        for (int e = 0; e < NEXP; e++) {
            g_counts[e]  = sc[e];
            g_offsets[e] = off;
            g_cursors[e] = off;
            off += sc[e];
        }
    }
    __syncthreads();
    for (int t = tid; t < NTOK; t += 256) {
#pragma unroll
        for (int k = 0; k < TOPKV; k++) {
            int e = g_topk_idx[t * 2 + k];
            int pos = atomicAdd(&g_cursors[e], 1);
            g_slot_token[pos] = t;
            g_slot_w[pos]     = g_topk_w[t * 2 + k];
        }
    }
}

// ---------------- tiled NT SGEMM (A row-major [M,K], B stored as [N,K]) ----
// MODE 0: A = gathered x rows, epilogue relu^2 -> g_hsq
// MODE 1: A = g_hsq slot rows, epilogue weight * atomicAdd into out
template <int KDIM, int NROWS, int MODE>
__global__ __launch_bounds__(256, 2)
void moe_gemm(const float* __restrict__ Asrc,   // x (MODE0), unused (MODE1)
              const float* __restrict__ Bsrc,   // W_fc (MODE0) / W_proj (MODE1)
              float* __restrict__ out)          // unused (MODE0) / output (MODE1)
{
    __shared__ float As[TKc][TM];
    __shared__ float Bs[TKc][TN];

    int e    = blockIdx.z;
    int cnt  = g_counts[e];
    int mbase = blockIdx.y * TM;
    if (mbase >= cnt) return;
    int base  = g_offsets[e];
    int nbase = blockIdx.x * TN;
    int tid   = threadIdx.x;

    // global->smem loading mapping: 128 rows x 8 k, one float4 per thread
    int lr = tid >> 1;            // tile row 0..127
    int lc = (tid & 1) * 4;       // k sub-offset 0 or 4

    bool aValid = (mbase + lr) < cnt;
    const float* aRow;
    if (MODE == 0) {
        int tok = aValid ? g_slot_token[base + mbase + lr] : 0;
        aRow = Asrc + (size_t)tok * KDIM;
    } else {
        int slot = aValid ? (base + mbase + lr) : 0;
        aRow = g_hsq + (size_t)slot * KDIM;
    }
    const float* bRow = Bsrc + ((size_t)e * NROWS + (nbase + lr)) * KDIM;

    int tx = tid & 15;            // col group
    int ty = tid >> 4;            // row group
    float acc[8][8] = {};

    for (int k0 = 0; k0 < KDIM; k0 += TKc) {
        float4 av = make_float4(0.f, 0.f, 0.f, 0.f);
        if (aValid) av = *(const float4*)(aRow + k0 + lc);
        float4 bv = *(const float4*)(bRow + k0 + lc);
        __syncthreads();
        As[lc + 0][lr] = av.x; As[lc + 1][lr] = av.y;
        As[lc + 2][lr] = av.z; As[lc + 3][lr] = av.w;
        Bs[lc + 0][lr] = bv.x; Bs[lc + 1][lr] = bv.y;
        Bs[lc + 2][lr] = bv.z; Bs[lc + 3][lr] = bv.w;
        __syncthreads();
#pragma unroll
        for (int kk = 0; kk < TKc; kk++) {
            float ra[8], rb[8];
            *(float4*)&ra[0] = *(const float4*)&As[kk][ty * 8 + 0];
            *(float4*)&ra[4] = *(const float4*)&As[kk][ty * 8 + 4];
            *(float4*)&rb[0] = *(const float4*)&Bs[kk][tx * 8 + 0];
            *(float4*)&rb[4] = *(const float4*)&Bs[kk][tx * 8 + 4];
#pragma unroll
            for (int i = 0; i < 8; i++)
#pragma unroll
                for (int j = 0; j < 8; j++)
                    acc[i][j] += ra[i] * rb[j];
        }
    }

#pragma unroll
    for (int i = 0; i < 8; i++) {
        int m = mbase + ty * 8 + i;
        if (m < cnt) {
            int slot = base + m;
            if (MODE == 0) {
                float* dst = g_hsq + (size_t)slot * HIDDENV + nbase + tx * 8;
                float4 v0, v1;
                float h;
                h = fmaxf(acc[i][0], 0.f); v0.x = h * h;
                h = fmaxf(acc[i][1], 0.f); v0.y = h * h;
                h = fmaxf(acc[i][2], 0.f); v0.z = h * h;
                h = fmaxf(acc[i][3], 0.f); v0.w = h * h;
                h = fmaxf(acc[i][4], 0.f); v1.x = h * h;
                h = fmaxf(acc[i][5], 0.f); v1.y = h * h;
                h = fmaxf(acc[i][6], 0.f); v1.z = h * h;
                h = fmaxf(acc[i][7], 0.f); v1.w = h * h;
                *(float4*)(dst + 0) = v0;
                *(float4*)(dst + 4) = v1;
            } else {
                int   tok = g_slot_token[slot];
                float w   = g_slot_w[slot];
                float* dst = out + (size_t)tok * DIMV + nbase + tx * 8;
#pragma unroll
                for (int j = 0; j < 8; j++)
                    atomicAdd(dst + j, w * acc[i][j]);
            }
        }
    }
}

// ---------------- launch ----------------
extern "C" void kernel_launch(void* const* d_in, const int* in_sizes, int n_in,
                              void* d_out, int out_size) {
    const float* x    = (const float*)d_in[0];  // [1,2048,1024]
    const float* Wr   = (const float*)d_in[1];  // [8,1024]
    const float* Wfc  = (const float*)d_in[2];  // [8,2048,1024]
    const float* Wpj  = (const float*)d_in[3];  // [8,1024,2048]
    float* out = (float*)d_out;

    // zero whole output buffer (covers main output + aux_loss tail)
    zero_kernel<<<(out_size + 255) / 256, 256>>>(out, out_size);

    // router: 4 tokens per 128-thread block
    router_kernel<<<NTOK / 4, 128>>>(x, Wr);

    // dispatch lists
    build_kernel<<<1, 256>>>();

    // fc: [n_e,1024] x [1024,2048]^T -> relu^2 -> g_hsq
    moe_gemm<DIMV, HIDDENV, 0>
        <<<dim3(HIDDENV / TN, NTOK / TM, NEXP), 256>>>(x, Wfc, nullptr);

    // proj: [n_e,2048] x [2048,1024]^T -> weighted accumulate into out
    moe_gemm<HIDDENV, DIMV, 1>
        <<<dim3(DIMV / TN, NTOK / TM, NEXP), 256>>>(nullptr, Wpj, out);
}

// round 10
// speedup vs baseline: 4.1792x; 4.1792x over previous
#include <cuda_runtime.h>
#include <cuda_bf16.h>
#include <math.h>

// ---------------- problem constants ----------------
#define DIMV      1024
#define HIDDENV   2048
#define NEXP      8
#define NTOK      2048
#define TOPKV     2
#define NSLOT     (NTOK * TOPKV)           // 4096

// ---------------- tcgen05 GEMM tiling ----------------
#define BM 128
#define BN 128
#define KC 64                              // bf16 elems per k-chunk = 128 bytes = 1 SW128 atom

#define SUB_BYTES   16384                  // 128 rows * 128 B
#define STAGE_BYTES (4 * SUB_BYTES)        // Ahi, Alo, Bhi, Blo
#define SMEM_TILES_OFF 1024
#define SMEM_TOTAL  (SMEM_TILES_OFF + 2 * STAGE_BYTES)   // 132096 B

// idesc: dtype=F32, atype=btype=BF16, N=128, M=128  (validated vs 0x8080490 N=32 case)
#define MMA_IDESC ((1u << 4) | (1u << 7) | (1u << 10) | ((BN / 8) << 17) | ((BM / 16) << 24))

// Arch-specific feature gate: tcgen05 only exists on the sm_103a/sm_100a passes.
#if defined(__CUDA_ARCH_FEAT_SM103_ALL) || defined(__CUDA_ARCH_FEAT_SM100_ALL) || defined(__CUDA_ARCH_FEAT_SM101_ALL)
#define HAS_TCGEN05 1
#else
#define HAS_TCGEN05 0
#endif

// ---------------- device scratch (no allocations allowed) ----------------
__device__ int   g_topk_idx[NSLOT];
__device__ float g_topk_w  [NSLOT];
__device__ int   g_counts  [NEXP];
__device__ int   g_offsets [NEXP];
__device__ int   g_cursors [NEXP];
__device__ int   g_slot_token[NSLOT];
__device__ float g_slot_w    [NSLOT];

__device__ __nv_bfloat16 g_wfc_hi[(size_t)NEXP * HIDDENV * DIMV];
__device__ __nv_bfloat16 g_wfc_lo[(size_t)NEXP * HIDDENV * DIMV];
__device__ __nv_bfloat16 g_wpj_hi[(size_t)NEXP * DIMV * HIDDENV];
__device__ __nv_bfloat16 g_wpj_lo[(size_t)NEXP * DIMV * HIDDENV];
__device__ __nv_bfloat16 g_a_hi[(size_t)NSLOT * DIMV];
__device__ __nv_bfloat16 g_a_lo[(size_t)NSLOT * DIMV];
__device__ __nv_bfloat16 g_h_hi[(size_t)NSLOT * HIDDENV];
__device__ __nv_bfloat16 g_h_lo[(size_t)NSLOT * HIDDENV];

// ---------------- arch-neutral helpers ----------------
__device__ __forceinline__ unsigned smem_u32(const void* p) {
    unsigned a;
    asm("{ .reg .u64 t; cvta.to.shared.u64 t, %1; cvt.u32.u64 %0, t; }" : "=r"(a) : "l"(p));
    return a;
}
__device__ __forceinline__ unsigned swz128(unsigned b) { return b ^ ((b >> 3) & 0x70); }

__device__ __forceinline__ void cp16(unsigned dst, const void* src) {
    asm volatile("cp.async.cg.shared.global [%0], [%1], 16;\n" :: "r"(dst), "l"(src) : "memory");
}
__device__ __forceinline__ void cp_commit() {
    asm volatile("cp.async.commit_group;\n" ::: "memory");
}
__device__ __forceinline__ void mbar_init(unsigned addr, unsigned cnt) {
    asm volatile("mbarrier.init.shared.b64 [%0], %1;" :: "r"(addr), "r"(cnt) : "memory");
}
__device__ __forceinline__ void mbar_wait(unsigned addr, unsigned parity) {
    unsigned done;
    asm volatile(
        "{\n\t.reg .pred p;\n\t"
        "mbarrier.try_wait.parity.acquire.cta.shared::cta.b64 p, [%1], %2;\n\t"
        "selp.b32 %0, 1, 0, p;\n\t}"
        : "=r"(done) : "r"(addr), "r"(parity) : "memory");
    if (!done) {
        asm volatile(
            "{\n\t.reg .pred P1;\n\t"
            "W_%=:\n\t"
            "mbarrier.try_wait.parity.acquire.cta.shared::cta.b64 P1, [%0], %1, 0x989680;\n\t"
            "@P1 bra.uni D_%=;\n\t"
            "bra.uni W_%=;\n\t"
            "D_%=:\n\t}"
            :: "r"(addr), "r"(parity) : "memory");
    }
}

// ---------------- tcgen05 helpers (only defined on the 'a' pass) ----------------
#if HAS_TCGEN05
__device__ __forceinline__ unsigned elect_one() {
    unsigned p;
    asm volatile("{\n\t.reg .pred p;\n\telect.sync _|p, 0xFFFFFFFF;\n\tselp.b32 %0, 1, 0, p;\n\t}" : "=r"(p));
    return p;
}
static __device__ __forceinline__ unsigned long long make_desc(unsigned addr) {
    // SW128, version=1 (Blackwell), SBO=64 (1024B per 8-row block), LBO=1 (16B)
    const unsigned long long base =
        (2ULL << 61) | (1ULL << 46) | (64ULL << 32) | (1ULL << 16);
    return base | ((unsigned long long)(addr >> 4) & 0x3FFF);
}
__device__ __forceinline__ void mma_f16_ss(unsigned d, unsigned long long a,
                                           unsigned long long b, unsigned idesc, unsigned acc) {
    asm volatile(
        "{\n\t.reg .pred p;\n\t"
        "setp.ne.u32 p, %4, 0;\n\t"
        "tcgen05.mma.cta_group::1.kind::f16 [%0], %1, %2, %3, {%5, %5, %5, %5}, p;\n\t"
        "}"
        :: "r"(d), "l"(a), "l"(b), "r"(idesc), "r"(acc), "r"(0u)
        : "memory");
}

#define TC_ALLOC(sa, n)   asm volatile("tcgen05.alloc.cta_group::1.sync.aligned.shared::cta.b32 [%0], %1;" :: "r"(sa), "r"(n) : "memory")
#define TC_DEALLOC(t, n)  asm volatile("tcgen05.dealloc.cta_group::1.sync.aligned.b32 %0, %1;" :: "r"(t), "r"(n))
#define TC_RELINQ()       asm volatile("tcgen05.relinquish_alloc_permit.cta_group::1.sync.aligned;")
#define TC_COMMIT(mb)     asm volatile("tcgen05.commit.cta_group::1.mbarrier::arrive::one.shared::cluster.b64 [%0];" :: "r"(mb) : "memory")
#define TC_FENCE_AFTER()  asm volatile("tcgen05.fence::after_thread_sync;" ::: "memory")
#define TC_FENCE_BEFORE() asm volatile("tcgen05.fence::before_thread_sync;" ::: "memory")
#define TC_WAIT_LD()      asm volatile("tcgen05.wait::ld.sync.aligned;" ::: "memory")
#define FENCE_PROXY()     asm volatile("fence.proxy.async.shared::cta;" ::: "memory")

#define LDTM_X32(r, a) \
    asm volatile( \
        "tcgen05.ld.sync.aligned.32x32b.x32.b32 " \
        "{%0, %1, %2, %3, %4, %5, %6, %7, " \
        " %8, %9, %10, %11, %12, %13, %14, %15, " \
        " %16, %17, %18, %19, %20, %21, %22, %23, " \
        " %24, %25, %26, %27, %28, %29, %30, %31}, [%32];" \
        : "=r"((r)[0]),  "=r"((r)[1]),  "=r"((r)[2]),  "=r"((r)[3]), \
          "=r"((r)[4]),  "=r"((r)[5]),  "=r"((r)[6]),  "=r"((r)[7]), \
          "=r"((r)[8]),  "=r"((r)[9]),  "=r"((r)[10]), "=r"((r)[11]), \
          "=r"((r)[12]), "=r"((r)[13]), "=r"((r)[14]), "=r"((r)[15]), \
          "=r"((r)[16]), "=r"((r)[17]), "=r"((r)[18]), "=r"((r)[19]), \
          "=r"((r)[20]), "=r"((r)[21]), "=r"((r)[22]), "=r"((r)[23]), \
          "=r"((r)[24]), "=r"((r)[25]), "=r"((r)[26]), "=r"((r)[27]), \
          "=r"((r)[28]), "=r"((r)[29]), "=r"((r)[30]), "=r"((r)[31]) \
        : "r"(a))
#endif  // HAS_TCGEN05

// ---------------- small kernels ----------------
__global__ void zero_kernel(float* __restrict__ out, int n) {
    int i = blockIdx.x * blockDim.x + threadIdx.x;
    if (i < n) out[i] = 0.0f;
}

__global__ __launch_bounds__(128)
void router_kernel(const float* __restrict__ x, const float* __restrict__ Wr) {
    __shared__ float sWr[NEXP * DIMV];
    int tid = threadIdx.x;
    for (int i = tid; i < NEXP * DIMV; i += 128) sWr[i] = Wr[i];
    __syncthreads();

    int warp = tid >> 5, lane = tid & 31;
    int t = blockIdx.x * 4 + warp;
    const float* xr = x + (size_t)t * DIMV;

    float xreg[DIMV / 32];
#pragma unroll
    for (int i = 0; i < DIMV / 32; i++) xreg[i] = xr[i * 32 + lane];

    float logits[NEXP];
#pragma unroll
    for (int e = 0; e < NEXP; e++) {
        float s = 0.f;
#pragma unroll
        for (int i = 0; i < DIMV / 32; i++) s += xreg[i] * sWr[e * DIMV + i * 32 + lane];
#pragma unroll
        for (int o = 16; o; o >>= 1) s += __shfl_xor_sync(0xffffffffu, s, o);
        logits[e] = s;
    }

    if (lane == 0) {
        float mx = logits[0];
#pragma unroll
        for (int e = 1; e < NEXP; e++) mx = fmaxf(mx, logits[e]);
        float p[NEXP], sum = 0.f;
#pragma unroll
        for (int e = 0; e < NEXP; e++) { p[e] = expf(logits[e] - mx); sum += p[e]; }
        float inv = 1.f / sum;
#pragma unroll
        for (int e = 0; e < NEXP; e++) p[e] *= inv;

        int i1 = -1, i2 = -1; float p1 = -1.f, p2 = -1.f;
#pragma unroll
        for (int e = 0; e < NEXP; e++) {
            if (p[e] > p1) { p2 = p1; i2 = i1; p1 = p[e]; i1 = e; }
            else if (p[e] > p2) { p2 = p[e]; i2 = e; }
        }
        float denom = p1 + p2 + 1e-8f;
        g_topk_idx[t * 2 + 0] = i1; g_topk_idx[t * 2 + 1] = i2;
        g_topk_w  [t * 2 + 0] = p1 / denom;
        g_topk_w  [t * 2 + 1] = p2 / denom;
    }
}

__global__ __launch_bounds__(256)
void build_kernel() {
    __shared__ int sc[NEXP];
    int tid = threadIdx.x;
    if (tid < NEXP) sc[tid] = 0;
    __syncthreads();
    for (int t = tid; t < NTOK; t += 256) {
        atomicAdd(&sc[g_topk_idx[t * 2 + 0]], 1);
        atomicAdd(&sc[g_topk_idx[t * 2 + 1]], 1);
    }
    __syncthreads();
    if (tid == 0) {
        int off = 0;
        for (int e = 0; e < NEXP; e++) {
            g_counts[e] = sc[e]; g_offsets[e] = off; g_cursors[e] = off; off += sc[e];
        }
    }
    __syncthreads();
    for (int t = tid; t < NTOK; t += 256) {
#pragma unroll
        for (int k = 0; k < TOPKV; k++) {
            int e = g_topk_idx[t * 2 + k];
            int pos = atomicAdd(&g_cursors[e], 1);
            g_slot_token[pos] = t;
            g_slot_w[pos]     = g_topk_w[t * 2 + k];
        }
    }
}

// fp32 -> bf16 hi/lo split, 4 elems per thread. W: 0 = fc weights, 1 = proj weights
template <int W>
__global__ __launch_bounds__(256)
void convert_w_kernel(const float* __restrict__ src) {
    __nv_bfloat16* hi = (W == 0) ? g_wfc_hi : g_wpj_hi;
    __nv_bfloat16* lo = (W == 0) ? g_wfc_lo : g_wpj_lo;
    size_t i = (size_t)blockIdx.x * blockDim.x + threadIdx.x;   // float4 index
    float4 v = ((const float4*)src)[i];
    float vv[4] = {v.x, v.y, v.z, v.w};
    unsigned ph[2], pl[2];
#pragma unroll
    for (int q = 0; q < 2; q++) {
        __nv_bfloat16 h0 = __float2bfloat16(vv[2 * q]);
        __nv_bfloat16 h1 = __float2bfloat16(vv[2 * q + 1]);
        __nv_bfloat16 l0 = __float2bfloat16(vv[2 * q] - __bfloat162float(h0));
        __nv_bfloat16 l1 = __float2bfloat16(vv[2 * q + 1] - __bfloat162float(h1));
        ph[q] = (unsigned)__bfloat16_as_ushort(h0) | ((unsigned)__bfloat16_as_ushort(h1) << 16);
        pl[q] = (unsigned)__bfloat16_as_ushort(l0) | ((unsigned)__bfloat16_as_ushort(l1) << 16);
    }
    ((uint2*)hi)[i] = make_uint2(ph[0], ph[1]);
    ((uint2*)lo)[i] = make_uint2(pl[0], pl[1]);
}

// gather token rows into slot-major bf16 hi/lo
__global__ __launch_bounds__(256)
void gather_x_kernel(const float* __restrict__ x) {
    int slot = blockIdx.x;
    int tok  = g_slot_token[slot];
    int i    = threadIdx.x;                       // float4 index within row
    float4 v = ((const float4*)(x + (size_t)tok * DIMV))[i];
    float vv[4] = {v.x, v.y, v.z, v.w};
    unsigned ph[2], pl[2];
#pragma unroll
    for (int q = 0; q < 2; q++) {
        __nv_bfloat16 h0 = __float2bfloat16(vv[2 * q]);
        __nv_bfloat16 h1 = __float2bfloat16(vv[2 * q + 1]);
        __nv_bfloat16 l0 = __float2bfloat16(vv[2 * q] - __bfloat162float(h0));
        __nv_bfloat16 l1 = __float2bfloat16(vv[2 * q + 1] - __bfloat162float(h1));
        ph[q] = (unsigned)__bfloat16_as_ushort(h0) | ((unsigned)__bfloat16_as_ushort(h1) << 16);
        pl[q] = (unsigned)__bfloat16_as_ushort(l0) | ((unsigned)__bfloat16_as_ushort(l1) << 16);
    }
    ((uint2*)(g_a_hi + (size_t)slot * DIMV))[i] = make_uint2(ph[0], ph[1]);
    ((uint2*)(g_a_lo + (size_t)slot * DIMV))[i] = make_uint2(pl[0], pl[1]);
}

// ---------------- grouped GEMM ----------------
// D[128 x 128] = A[128 x KDIM] * B[KDIM x 128]^T   (B stored [N,K] K-major)
// 3-term bf16 split accumulated in fp32.
// MODE 0: A = g_a (gathered x),  B = W_fc,   epilogue relu^2 -> g_h hi/lo
// MODE 1: A = g_h,               B = W_proj, epilogue weighted atomicAdd -> out
template <int KDIM, int NROWS, int MODE>
__global__ __launch_bounds__(128, 1)
void moe_gemm_tc(float* __restrict__ out) {
    int e     = blockIdx.z;
    int cnt   = g_counts[e];
    int mbase = blockIdx.y * BM;
    if (mbase >= cnt) return;
    int base  = g_offsets[e];
    int nbase = blockIdx.x * BN;

    const __nv_bfloat16* Ahi = (MODE == 0) ? g_a_hi : g_h_hi;
    const __nv_bfloat16* Alo = (MODE == 0) ? g_a_lo : g_h_lo;
    const __nv_bfloat16* Bhi = (MODE == 0) ? g_wfc_hi : g_wpj_hi;
    const __nv_bfloat16* Blo = (MODE == 0) ? g_wfc_lo : g_wpj_lo;

    extern __shared__ char smem[];
    int tid = threadIdx.x, wid = tid >> 5, lid = tid & 31;

#if HAS_TCGEN05
    // =================== tcgen05 path (sm_103a cubin) ===================
    unsigned sb = smem_u32(smem);

    if (tid == 0) { mbar_init(sb + 8, 1); mbar_init(sb + 16, 1); }
    if (wid == 0) { TC_ALLOC(sb, 128); TC_RELINQ(); }
    __syncthreads();
    unsigned tmem;
    asm volatile("ld.shared.b32 %0, [%1];" : "=r"(tmem) : "r"(sb));

    // per-thread load geometry (rows fixed across k-chunks)
    int c16 = tid & 7;            // 16B chunk within the 128B row
    int r0  = tid >> 3;           // base row; rows r0 + 16*j
    size_t aoff[8], boff[8];
    unsigned dsw[8];
#pragma unroll
    for (int j = 0; j < 8; j++) {
        int r = r0 + 16 * j;
        int arow = base + mbase + r; if (arow > NSLOT - 1) arow = NSLOT - 1;
        aoff[j] = (size_t)arow * KDIM + c16 * 8;
        boff[j] = ((size_t)e * NROWS + (nbase + r)) * KDIM + c16 * 8;
        dsw[j]  = swz128((unsigned)(r * 128 + c16 * 16));
    }

    const int NC = KDIM / KC;
    int ph[2] = {0, 0};

    // prologue: load chunk 0 into stage 0
    {
        unsigned st = sb + SMEM_TILES_OFF;
#pragma unroll
        for (int j = 0; j < 8; j++) {
            cp16(st + dsw[j],                 Ahi + aoff[j]);
            cp16(st + SUB_BYTES + dsw[j],     Alo + aoff[j]);
            cp16(st + 2 * SUB_BYTES + dsw[j], Bhi + boff[j]);
            cp16(st + 3 * SUB_BYTES + dsw[j], Blo + boff[j]);
        }
        cp_commit();
    }

    for (int i = 0; i < NC; i++) {
        int s = i & 1;
        if (i + 1 < NC) {
            int b = s ^ 1;
            if (i >= 1) { mbar_wait(sb + 8 + b * 8, ph[b]); ph[b] ^= 1; }
            unsigned st = sb + SMEM_TILES_OFF + b * STAGE_BYTES;
            size_t k0 = (size_t)(i + 1) * KC;
#pragma unroll
            for (int j = 0; j < 8; j++) {
                cp16(st + dsw[j],                 Ahi + aoff[j] + k0);
                cp16(st + SUB_BYTES + dsw[j],     Alo + aoff[j] + k0);
                cp16(st + 2 * SUB_BYTES + dsw[j], Bhi + boff[j] + k0);
                cp16(st + 3 * SUB_BYTES + dsw[j], Blo + boff[j] + k0);
            }
            cp_commit();
            asm volatile("cp.async.wait_group 1;\n" ::: "memory");
        } else {
            asm volatile("cp.async.wait_group 0;\n" ::: "memory");
        }
        FENCE_PROXY();
        __syncthreads();

        if (wid == 0) {
            if (elect_one()) {
                unsigned st = sb + SMEM_TILES_OFF + s * STAGE_BYTES;
                unsigned long long dAh = make_desc(st);
                unsigned long long dAl = make_desc(st + SUB_BYTES);
                unsigned long long dBh = make_desc(st + 2 * SUB_BYTES);
                unsigned long long dBl = make_desc(st + 3 * SUB_BYTES);
#pragma unroll
                for (int sub = 0; sub < 4; sub++) {
                    unsigned o = sub * 2;   // +32 bytes per 16-bf16 k-step
                    mma_f16_ss(tmem, dAh + o, dBh + o, MMA_IDESC, (i > 0) || (sub > 0));
                    mma_f16_ss(tmem, dAl + o, dBh + o, MMA_IDESC, 1u);
                    mma_f16_ss(tmem, dAh + o, dBl + o, MMA_IDESC, 1u);
                }
                TC_COMMIT(sb + 8 + s * 8);
            }
        }
    }

    // wait for last chunk's MMAs (commit tracks all prior MMAs)
    {
        int b = (NC - 1) & 1;
        mbar_wait(sb + 8 + b * 8, ph[b]); ph[b] ^= 1;
    }
    TC_FENCE_AFTER();

    // epilogue
    int m = mbase + wid * 32 + lid;
    bool valid = (m < cnt);
    int slot = base + (valid ? m : 0);
    float w = 0.f; int tok = 0;
    if (MODE == 1 && valid) { w = g_slot_w[slot]; tok = g_slot_token[slot]; }

#pragma unroll
    for (int gq = 0; gq < 4; gq++) {
        unsigned r[32];
        LDTM_X32(r, tmem + gq * 32);
        TC_WAIT_LD();
        if (valid) {
            if (MODE == 0) {
                unsigned phh[16], pll[16];
#pragma unroll
                for (int j = 0; j < 16; j++) {
                    float v0 = fmaxf(__uint_as_float(r[2 * j]), 0.f);     v0 *= v0;
                    float v1 = fmaxf(__uint_as_float(r[2 * j + 1]), 0.f); v1 *= v1;
                    __nv_bfloat16 h0 = __float2bfloat16(v0);
                    __nv_bfloat16 h1 = __float2bfloat16(v1);
                    __nv_bfloat16 l0 = __float2bfloat16(v0 - __bfloat162float(h0));
                    __nv_bfloat16 l1 = __float2bfloat16(v1 - __bfloat162float(h1));
                    phh[j] = (unsigned)__bfloat16_as_ushort(h0) | ((unsigned)__bfloat16_as_ushort(h1) << 16);
                    pll[j] = (unsigned)__bfloat16_as_ushort(l0) | ((unsigned)__bfloat16_as_ushort(l1) << 16);
                }
                uint4* dh = (uint4*)(g_h_hi + (size_t)slot * HIDDENV + nbase + gq * 32);
                uint4* dl = (uint4*)(g_h_lo + (size_t)slot * HIDDENV + nbase + gq * 32);
#pragma unroll
                for (int q = 0; q < 4; q++) {
                    dh[q] = make_uint4(phh[4 * q], phh[4 * q + 1], phh[4 * q + 2], phh[4 * q + 3]);
                    dl[q] = make_uint4(pll[4 * q], pll[4 * q + 1], pll[4 * q + 2], pll[4 * q + 3]);
                }
            } else {
                float* dst = out + (size_t)tok * DIMV + nbase + gq * 32;
#pragma unroll
                for (int j = 0; j < 32; j++)
                    atomicAdd(dst + j, w * __uint_as_float(r[j]));
            }
        }
    }

    TC_FENCE_BEFORE();
    __syncthreads();
    if (tid == 0) {
        asm volatile("mbarrier.inval.shared.b64 [%0];" :: "r"(sb + 8) : "memory");
        asm volatile("mbarrier.inval.shared.b64 [%0];" :: "r"(sb + 16) : "memory");
    }
    __syncthreads();
    if (wid == 0) TC_DEALLOC(tmem, 128);

#else
    // ============ plain-CUDA fallback (non-'a' gencode pass only) ============
    // One thread per M row; B column tile broadcast via smem. Correct, not fast —
    // at runtime the exact-match sm_103a cubin (tcgen05 path) is what loads.
    (void)wid; (void)lid;
    float* Bsh = (float*)smem;              // 128 floats per k
    int m = mbase + tid;
    bool valid = (m < cnt);
    int arow = base + (valid ? m : 0);
    const __nv_bfloat16* ah = Ahi + (size_t)arow * KDIM;
    const __nv_bfloat16* al = Alo + (size_t)arow * KDIM;

    float acc[BN];
#pragma unroll
    for (int c = 0; c < BN; c++) acc[c] = 0.f;

    for (int k = 0; k < KDIM; k++) {
        __syncthreads();
        {
            size_t bi = ((size_t)e * NROWS + (nbase + tid)) * KDIM + k;
            Bsh[tid] = __bfloat162float(Bhi[bi]) + __bfloat162float(Blo[bi]);
        }
        __syncthreads();
        float a = __bfloat162float(ah[k]) + __bfloat162float(al[k]);
#pragma unroll 8
        for (int c = 0; c < BN; c++) acc[c] += a * Bsh[c];
    }

    if (valid) {
        int slot = base + m;
        if (MODE == 0) {
            __nv_bfloat16* dh = g_h_hi + (size_t)slot * HIDDENV + nbase;
            __nv_bfloat16* dl = g_h_lo + (size_t)slot * HIDDENV + nbase;
            for (int c = 0; c < BN; c++) {
                float v = fmaxf(acc[c], 0.f); v *= v;
                __nv_bfloat16 h = __float2bfloat16(v);
                dh[c] = h;
                dl[c] = __float2bfloat16(v - __bfloat162float(h));
            }
        } else {
            int   tok = g_slot_token[slot];
            float w   = g_slot_w[slot];
            float* dst = out + (size_t)tok * DIMV + nbase;
            for (int c = 0; c < BN; c++) atomicAdd(dst + c, w * acc[c]);
        }
    }
#endif
}

// ---------------- launch ----------------
extern "C" void kernel_launch(void* const* d_in, const int* in_sizes, int n_in,
                              void* d_out, int out_size) {
    const float* x   = (const float*)d_in[0];  // [1,2048,1024]
    const float* Wr  = (const float*)d_in[1];  // [8,1024]
    const float* Wfc = (const float*)d_in[2];  // [8,2048,1024]
    const float* Wpj = (const float*)d_in[3];  // [8,1024,2048]
    float* out = (float*)d_out;

    cudaFuncSetAttribute(moe_gemm_tc<DIMV, HIDDENV, 0>,
                         cudaFuncAttributeMaxDynamicSharedMemorySize, SMEM_TOTAL);
    cudaFuncSetAttribute(moe_gemm_tc<HIDDENV, DIMV, 1>,
                         cudaFuncAttributeMaxDynamicSharedMemorySize, SMEM_TOTAL);

    zero_kernel<<<(out_size + 255) / 256, 256>>>(out, out_size);
    router_kernel<<<NTOK / 4, 128>>>(x, Wr);
    build_kernel<<<1, 256>>>();

    // split weights into bf16 hi/lo
    const int n4 = NEXP * HIDDENV * DIMV / 4;
    convert_w_kernel<0><<<n4 / 256, 256>>>(Wfc);
    convert_w_kernel<1><<<n4 / 256, 256>>>(Wpj);

    // gather + split activations per slot
    gather_x_kernel<<<NSLOT, 256>>>(x);

    // fc GEMM: [cnt x 1024] * [1024 x 2048] -> relu^2 -> g_h hi/lo
    moe_gemm_tc<DIMV, HIDDENV, 0>
        <<<dim3(HIDDENV / BN, NSLOT / BM, NEXP), 128, SMEM_TOTAL>>>(nullptr);

    // proj GEMM: [cnt x 2048] * [2048 x 1024] -> weighted accumulate -> out
    moe_gemm_tc<HIDDENV, DIMV, 1>
        <<<dim3(DIMV / BN, NSLOT / BM, NEXP), 128, SMEM_TOTAL>>>(out);
}

// round 15
// speedup vs baseline: 4.6324x; 1.1085x over previous
#include <cuda_runtime.h>
#include <cuda_bf16.h>
#include <math.h>

// ---------------- problem constants ----------------
#define DIMV      1024
#define HIDDENV   2048
#define NEXP      8
#define NTOK      2048
#define TOPKV     2
#define NSLOT     (NTOK * TOPKV)           // 4096

// ---------------- tcgen05 GEMM tiling ----------------
#define BM 128
#define BN 256
#define KC 64                              // bf16 elems per k-chunk = 128 B = 1 SW128 atom

#define A_SUB_BYTES 16384                  // 128 rows * 128 B
#define B_SUB_BYTES 32768                  // 256 rows * 128 B
#define STAGE_BYTES (2 * A_SUB_BYTES + 2 * B_SUB_BYTES)   // 98304
#define SMEM_TILES_OFF 1024
#define SMEM_TOTAL  (SMEM_TILES_OFF + 2 * STAGE_BYTES)    // 197632 B

// stage-relative offsets
#define OFF_AHI 0
#define OFF_ALO (A_SUB_BYTES)
#define OFF_BHI (2 * A_SUB_BYTES)
#define OFF_BLO (2 * A_SUB_BYTES + B_SUB_BYTES)

// idesc: dtype=F32, atype=btype=BF16, N=256, M=128
#define MMA_IDESC ((1u << 4) | (1u << 7) | (1u << 10) | ((BN / 8) << 17) | ((BM / 16) << 24))

#define TMEM_COLS 256

// Arch-specific feature gate: tcgen05 only exists on the sm_103a/sm_100a passes.
#if defined(__CUDA_ARCH_FEAT_SM103_ALL) || defined(__CUDA_ARCH_FEAT_SM100_ALL) || defined(__CUDA_ARCH_FEAT_SM101_ALL)
#define HAS_TCGEN05 1
#else
#define HAS_TCGEN05 0
#endif

// ---------------- device scratch (no allocations allowed) ----------------
__device__ int   g_topk_idx[NSLOT];
__device__ float g_topk_w  [NSLOT];
__device__ int   g_counts  [NEXP];
__device__ int   g_offsets [NEXP];
__device__ int   g_cursors [NEXP];
__device__ int   g_slot_token[NSLOT];
__device__ float g_slot_w    [NSLOT];

__device__ __nv_bfloat16 g_wfc_hi[(size_t)NEXP * HIDDENV * DIMV];
__device__ __nv_bfloat16 g_wfc_lo[(size_t)NEXP * HIDDENV * DIMV];
__device__ __nv_bfloat16 g_wpj_hi[(size_t)NEXP * DIMV * HIDDENV];
__device__ __nv_bfloat16 g_wpj_lo[(size_t)NEXP * DIMV * HIDDENV];
__device__ __nv_bfloat16 g_a_hi[(size_t)NSLOT * DIMV];
__device__ __nv_bfloat16 g_a_lo[(size_t)NSLOT * DIMV];
__device__ __nv_bfloat16 g_h_hi[(size_t)NSLOT * HIDDENV];
__device__ __nv_bfloat16 g_h_lo[(size_t)NSLOT * HIDDENV];

// ---------------- arch-neutral helpers ----------------
__device__ __forceinline__ unsigned smem_u32(const void* p) {
    unsigned a;
    asm("{ .reg .u64 t; cvta.to.shared.u64 t, %1; cvt.u32.u64 %0, t; }" : "=r"(a) : "l"(p));
    return a;
}
__device__ __forceinline__ unsigned swz128(unsigned b) { return b ^ ((b >> 3) & 0x70); }

__device__ __forceinline__ void cp16(unsigned dst, const void* src) {
    asm volatile("cp.async.cg.shared.global [%0], [%1], 16;\n" :: "r"(dst), "l"(src) : "memory");
}
__device__ __forceinline__ void cp_commit() {
    asm volatile("cp.async.commit_group;\n" ::: "memory");
}
__device__ __forceinline__ void mbar_init(unsigned addr, unsigned cnt) {
    asm volatile("mbarrier.init.shared.b64 [%0], %1;" :: "r"(addr), "r"(cnt) : "memory");
}
__device__ __forceinline__ void mbar_wait(unsigned addr, unsigned parity) {
    unsigned done;
    asm volatile(
        "{\n\t.reg .pred p;\n\t"
        "mbarrier.try_wait.parity.acquire.cta.shared::cta.b64 p, [%1], %2;\n\t"
        "selp.b32 %0, 1, 0, p;\n\t}"
        : "=r"(done) : "r"(addr), "r"(parity) : "memory");
    if (!done) {
        asm volatile(
            "{\n\t.reg .pred P1;\n\t"
            "W_%=:\n\t"
            "mbarrier.try_wait.parity.acquire.cta.shared::cta.b64 P1, [%0], %1, 0x989680;\n\t"
            "@P1 bra.uni D_%=;\n\t"
            "bra.uni W_%=;\n\t"
            "D_%=:\n\t}"
            :: "r"(addr), "r"(parity) : "memory");
    }
}

// ---------------- tcgen05 helpers (only defined on the 'a' pass) ----------------
#if HAS_TCGEN05
__device__ __forceinline__ unsigned elect_one() {
    unsigned p;
    asm volatile("{\n\t.reg .pred p;\n\telect.sync _|p, 0xFFFFFFFF;\n\tselp.b32 %0, 1, 0, p;\n\t}" : "=r"(p));
    return p;
}
static __device__ __forceinline__ unsigned long long make_desc(unsigned addr) {
    // SW128, version=1 (Blackwell), SBO=64 (1024B per 8-row block), LBO=1 (16B)
    const unsigned long long base =
        (2ULL << 61) | (1ULL << 46) | (64ULL << 32) | (1ULL << 16);
    return base | ((unsigned long long)(addr >> 4) & 0x3FFF);
}
__device__ __forceinline__ void mma_f16_ss(unsigned d, unsigned long long a,
                                           unsigned long long b, unsigned idesc, unsigned acc) {
    asm volatile(
        "{\n\t.reg .pred p;\n\t"
        "setp.ne.u32 p, %4, 0;\n\t"
        "tcgen05.mma.cta_group::1.kind::f16 [%0], %1, %2, %3, {%5, %5, %5, %5}, p;\n\t"
        "}"
        :: "r"(d), "l"(a), "l"(b), "r"(idesc), "r"(acc), "r"(0u)
        : "memory");
}

#define TC_ALLOC(sa, n)   asm volatile("tcgen05.alloc.cta_group::1.sync.aligned.shared::cta.b32 [%0], %1;" :: "r"(sa), "r"(n) : "memory")
#define TC_DEALLOC(t, n)  asm volatile("tcgen05.dealloc.cta_group::1.sync.aligned.b32 %0, %1;" :: "r"(t), "r"(n))
#define TC_RELINQ()       asm volatile("tcgen05.relinquish_alloc_permit.cta_group::1.sync.aligned;")
#define TC_COMMIT(mb)     asm volatile("tcgen05.commit.cta_group::1.mbarrier::arrive::one.shared::cluster.b64 [%0];" :: "r"(mb) : "memory")
#define TC_FENCE_AFTER()  asm volatile("tcgen05.fence::after_thread_sync;" ::: "memory")
#define TC_FENCE_BEFORE() asm volatile("tcgen05.fence::before_thread_sync;" ::: "memory")
#define TC_WAIT_LD()      asm volatile("tcgen05.wait::ld.sync.aligned;" ::: "memory")
#define FENCE_PROXY()     asm volatile("fence.proxy.async.shared::cta;" ::: "memory")

#define LDTM_X32(r, a) \
    asm volatile( \
        "tcgen05.ld.sync.aligned.32x32b.x32.b32 " \
        "{%0, %1, %2, %3, %4, %5, %6, %7, " \
        " %8, %9, %10, %11, %12, %13, %14, %15, " \
        " %16, %17, %18, %19, %20, %21, %22, %23, " \
        " %24, %25, %26, %27, %28, %29, %30, %31}, [%32];" \
        : "=r"((r)[0]),  "=r"((r)[1]),  "=r"((r)[2]),  "=r"((r)[3]), \
          "=r"((r)[4]),  "=r"((r)[5]),  "=r"((r)[6]),  "=r"((r)[7]), \
          "=r"((r)[8]),  "=r"((r)[9]),  "=r"((r)[10]), "=r"((r)[11]), \
          "=r"((r)[12]), "=r"((r)[13]), "=r"((r)[14]), "=r"((r)[15]), \
          "=r"((r)[16]), "=r"((r)[17]), "=r"((r)[18]), "=r"((r)[19]), \
          "=r"((r)[20]), "=r"((r)[21]), "=r"((r)[22]), "=r"((r)[23]), \
          "=r"((r)[24]), "=r"((r)[25]), "=r"((r)[26]), "=r"((r)[27]), \
          "=r"((r)[28]), "=r"((r)[29]), "=r"((r)[30]), "=r"((r)[31]) \
        : "r"(a))
#endif  // HAS_TCGEN05

// ---------------- small kernels ----------------
__global__ void zero_kernel(float* __restrict__ out, int n) {
    int i = blockIdx.x * blockDim.x + threadIdx.x;
    if (i < n) out[i] = 0.0f;
}

__global__ __launch_bounds__(128)
void router_kernel(const float* __restrict__ x, const float* __restrict__ Wr) {
    __shared__ float sWr[NEXP * DIMV];
    int tid = threadIdx.x;
    for (int i = tid; i < NEXP * DIMV; i += 128) sWr[i] = Wr[i];
    __syncthreads();

    int warp = tid >> 5, lane = tid & 31;
    int t = blockIdx.x * 4 + warp;
    const float* xr = x + (size_t)t * DIMV;

    float xreg[DIMV / 32];
#pragma unroll
    for (int i = 0; i < DIMV / 32; i++) xreg[i] = xr[i * 32 + lane];

    float logits[NEXP];
#pragma unroll
    for (int e = 0; e < NEXP; e++) {
        float s = 0.f;
#pragma unroll
        for (int i = 0; i < DIMV / 32; i++) s += xreg[i] * sWr[e * DIMV + i * 32 + lane];
#pragma unroll
        for (int o = 16; o; o >>= 1) s += __shfl_xor_sync(0xffffffffu, s, o);
        logits[e] = s;
    }

    if (lane == 0) {
        float mx = logits[0];
#pragma unroll
        for (int e = 1; e < NEXP; e++) mx = fmaxf(mx, logits[e]);
        float p[NEXP], sum = 0.f;
#pragma unroll
        for (int e = 0; e < NEXP; e++) { p[e] = expf(logits[e] - mx); sum += p[e]; }
        float inv = 1.f / sum;
#pragma unroll
        for (int e = 0; e < NEXP; e++) p[e] *= inv;

        int i1 = -1, i2 = -1; float p1 = -1.f, p2 = -1.f;
#pragma unroll
        for (int e = 0; e < NEXP; e++) {
            if (p[e] > p1) { p2 = p1; i2 = i1; p1 = p[e]; i1 = e; }
            else if (p[e] > p2) { p2 = p[e]; i2 = e; }
        }
        float denom = p1 + p2 + 1e-8f;
        g_topk_idx[t * 2 + 0] = i1; g_topk_idx[t * 2 + 1] = i2;
        g_topk_w  [t * 2 + 0] = p1 / denom;
        g_topk_w  [t * 2 + 1] = p2 / denom;
    }
}

__global__ __launch_bounds__(256)
void build_kernel() {
    __shared__ int sc[NEXP];
    int tid = threadIdx.x;
    if (tid < NEXP) sc[tid] = 0;
    __syncthreads();
    for (int t = tid; t < NTOK; t += 256) {
        atomicAdd(&sc[g_topk_idx[t * 2 + 0]], 1);
        atomicAdd(&sc[g_topk_idx[t * 2 + 1]], 1);
    }
    __syncthreads();
    if (tid == 0) {
        int off = 0;
        for (int e = 0; e < NEXP; e++) {
            g_counts[e] = sc[e]; g_offsets[e] = off; g_cursors[e] = off; off += sc[e];
        }
    }
    __syncthreads();
    for (int t = tid; t < NTOK; t += 256) {
#pragma unroll
        for (int k = 0; k < TOPKV; k++) {
            int e = g_topk_idx[t * 2 + k];
            int pos = atomicAdd(&g_cursors[e], 1);
            g_slot_token[pos] = t;
            g_slot_w[pos]     = g_topk_w[t * 2 + k];
        }
    }
}

// fp32 -> bf16 hi/lo split, 8 elems (2 float4) per thread. W: 0 = fc, 1 = proj
template <int W>
__global__ __launch_bounds__(256)
void convert_w_kernel(const float* __restrict__ src) {
    __nv_bfloat16* hi = (W == 0) ? g_wfc_hi : g_wpj_hi;
    __nv_bfloat16* lo = (W == 0) ? g_wfc_lo : g_wpj_lo;
    size_t i0 = ((size_t)blockIdx.x * blockDim.x + threadIdx.x) * 2;  // float4 index
#pragma unroll
    for (int u = 0; u < 2; u++) {
        size_t i = i0 + u;
        float4 v = ((const float4*)src)[i];
        float vv[4] = {v.x, v.y, v.z, v.w};
        unsigned ph[2], pl[2];
#pragma unroll
        for (int q = 0; q < 2; q++) {
            __nv_bfloat16 h0 = __float2bfloat16(vv[2 * q]);
            __nv_bfloat16 h1 = __float2bfloat16(vv[2 * q + 1]);
            __nv_bfloat16 l0 = __float2bfloat16(vv[2 * q] - __bfloat162float(h0));
            __nv_bfloat16 l1 = __float2bfloat16(vv[2 * q + 1] - __bfloat162float(h1));
            ph[q] = (unsigned)__bfloat16_as_ushort(h0) | ((unsigned)__bfloat16_as_ushort(h1) << 16);
            pl[q] = (unsigned)__bfloat16_as_ushort(l0) | ((unsigned)__bfloat16_as_ushort(l1) << 16);
        }
        ((uint2*)hi)[i] = make_uint2(ph[0], ph[1]);
        ((uint2*)lo)[i] = make_uint2(pl[0], pl[1]);
    }
}

// gather token rows into slot-major bf16 hi/lo
__global__ __launch_bounds__(256)
void gather_x_kernel(const float* __restrict__ x) {
    int slot = blockIdx.x;
    int tok  = g_slot_token[slot];
    int i    = threadIdx.x;                       // float4 index within row
    float4 v = ((const float4*)(x + (size_t)tok * DIMV))[i];
    float vv[4] = {v.x, v.y, v.z, v.w};
    unsigned ph[2], pl[2];
#pragma unroll
    for (int q = 0; q < 2; q++) {
        __nv_bfloat16 h0 = __float2bfloat16(vv[2 * q]);
        __nv_bfloat16 h1 = __float2bfloat16(vv[2 * q + 1]);
        __nv_bfloat16 l0 = __float2bfloat16(vv[2 * q] - __bfloat162float(h0));
        __nv_bfloat16 l1 = __float2bfloat16(vv[2 * q + 1] - __bfloat162float(h1));
        ph[q] = (unsigned)__bfloat16_as_ushort(h0) | ((unsigned)__bfloat16_as_ushort(h1) << 16);
        pl[q] = (unsigned)__bfloat16_as_ushort(l0) | ((unsigned)__bfloat16_as_ushort(l1) << 16);
    }
    ((uint2*)(g_a_hi + (size_t)slot * DIMV))[i] = make_uint2(ph[0], ph[1]);
    ((uint2*)(g_a_lo + (size_t)slot * DIMV))[i] = make_uint2(pl[0], pl[1]);
}

// ---------------- grouped GEMM ----------------
// D[128 x 256] = A[128 x KDIM] * B[KDIM x 256]^T   (B stored [N,K] K-major)
// 3-term bf16 split accumulated in fp32 (TMEM).
// MODE 0: A = g_a (gathered x),  B = W_fc,   epilogue relu^2 -> g_h hi/lo
// MODE 1: A = g_h,               B = W_proj, epilogue weighted atomicAdd -> out
template <int KDIM, int NROWS, int MODE>
__global__ __launch_bounds__(128, 1)
void moe_gemm_tc(float* __restrict__ out) {
    int e     = blockIdx.z;
    int cnt   = g_counts[e];
    int mbase = blockIdx.y * BM;
    if (mbase >= cnt) return;
    int base  = g_offsets[e];
    int nbase = blockIdx.x * BN;

    const __nv_bfloat16* Ahi = (MODE == 0) ? g_a_hi : g_h_hi;
    const __nv_bfloat16* Alo = (MODE == 0) ? g_a_lo : g_h_lo;
    const __nv_bfloat16* Bhi = (MODE == 0) ? g_wfc_hi : g_wpj_hi;
    const __nv_bfloat16* Blo = (MODE == 0) ? g_wfc_lo : g_wpj_lo;

    extern __shared__ char smem[];
    int tid = threadIdx.x, wid = tid >> 5, lid = tid & 31;

#if HAS_TCGEN05
    // =================== tcgen05 path (sm_103a cubin) ===================
    unsigned sb = smem_u32(smem);

    if (tid == 0) { mbar_init(sb + 8, 1); mbar_init(sb + 16, 1); }
    if (wid == 0) { TC_ALLOC(sb, TMEM_COLS); TC_RELINQ(); }
    __syncthreads();
    unsigned tmem;
    asm volatile("ld.shared.b32 %0, [%1];" : "=r"(tmem) : "r"(sb));

    // per-thread load geometry (rows fixed across k-chunks)
    int c16 = tid & 7;            // 16B chunk within the 128B row
    int r0  = tid >> 3;           // base row (0..15); A rows r0+16j (j<8), B rows r0+16j (j<16)
    size_t aoff[8];
    unsigned daw[8];
#pragma unroll
    for (int j = 0; j < 8; j++) {
        int r = r0 + 16 * j;
        int arow = base + mbase + r; if (arow > NSLOT - 1) arow = NSLOT - 1;
        aoff[j] = (size_t)arow * KDIM + c16 * 8;
        daw[j]  = swz128((unsigned)(r * 128 + c16 * 16));
    }
    size_t boff[16];
    unsigned dbw[16];
#pragma unroll
    for (int j = 0; j < 16; j++) {
        int r = r0 + 16 * j;      // 0..255
        boff[j] = ((size_t)e * NROWS + (nbase + r)) * KDIM + c16 * 8;
        dbw[j]  = swz128((unsigned)(r * 128 + c16 * 16));
    }

    const int NC = KDIM / KC;
    int ph[2] = {0, 0};

    // prologue: load chunk 0 into stage 0
    {
        unsigned st = sb + SMEM_TILES_OFF;
#pragma unroll
        for (int j = 0; j < 8; j++) {
            cp16(st + OFF_AHI + daw[j], Ahi + aoff[j]);
            cp16(st + OFF_ALO + daw[j], Alo + aoff[j]);
        }
#pragma unroll
        for (int j = 0; j < 16; j++) {
            cp16(st + OFF_BHI + dbw[j], Bhi + boff[j]);
            cp16(st + OFF_BLO + dbw[j], Blo + boff[j]);
        }
        cp_commit();
    }

    for (int i = 0; i < NC; i++) {
        int s = i & 1;
        if (i + 1 < NC) {
            int b = s ^ 1;
            if (i >= 1) { mbar_wait(sb + 8 + b * 8, ph[b]); ph[b] ^= 1; }
            unsigned st = sb + SMEM_TILES_OFF + b * STAGE_BYTES;
            size_t k0 = (size_t)(i + 1) * KC;
#pragma unroll
            for (int j = 0; j < 8; j++) {
                cp16(st + OFF_AHI + daw[j], Ahi + aoff[j] + k0);
                cp16(st + OFF_ALO + daw[j], Alo + aoff[j] + k0);
            }
#pragma unroll
            for (int j = 0; j < 16; j++) {
                cp16(st + OFF_BHI + dbw[j], Bhi + boff[j] + k0);
                cp16(st + OFF_BLO + dbw[j], Blo + boff[j] + k0);
            }
            cp_commit();
            asm volatile("cp.async.wait_group 1;\n" ::: "memory");
        } else {
            asm volatile("cp.async.wait_group 0;\n" ::: "memory");
        }
        FENCE_PROXY();
        __syncthreads();

        if (wid == 0) {
            if (elect_one()) {
                unsigned st = sb + SMEM_TILES_OFF + s * STAGE_BYTES;
                unsigned long long dAh = make_desc(st + OFF_AHI);
                unsigned long long dAl = make_desc(st + OFF_ALO);
                unsigned long long dBh = make_desc(st + OFF_BHI);
                unsigned long long dBl = make_desc(st + OFF_BLO);
#pragma unroll
                for (int sub = 0; sub < 4; sub++) {
                    unsigned o = sub * 2;   // +32 bytes per 16-bf16 k-step
                    mma_f16_ss(tmem, dAh + o, dBh + o, MMA_IDESC, (i > 0) || (sub > 0));
                    mma_f16_ss(tmem, dAl + o, dBh + o, MMA_IDESC, 1u);
                    mma_f16_ss(tmem, dAh + o, dBl + o, MMA_IDESC, 1u);
                }
                TC_COMMIT(sb + 8 + s * 8);
            }
        }
    }

    // wait for last chunk's MMAs
    {
        int b = (NC - 1) & 1;
        mbar_wait(sb + 8 + b * 8, ph[b]); ph[b] ^= 1;
    }
    TC_FENCE_AFTER();

    // epilogue
    int m = mbase + wid * 32 + lid;
    bool valid = (m < cnt);
    int slot = base + (valid ? m : 0);
    float w = 0.f; int tok = 0;
    if (MODE == 1 && valid) { w = g_slot_w[slot]; tok = g_slot_token[slot]; }

#pragma unroll
    for (int gq = 0; gq < BN / 32; gq++) {
        unsigned r[32];
        LDTM_X32(r, tmem + gq * 32);
        TC_WAIT_LD();
        if (valid) {
            if (MODE == 0) {
                unsigned phh[16], pll[16];
#pragma unroll
                for (int j = 0; j < 16; j++) {
                    float v0 = fmaxf(__uint_as_float(r[2 * j]), 0.f);     v0 *= v0;
                    float v1 = fmaxf(__uint_as_float(r[2 * j + 1]), 0.f); v1 *= v1;
                    __nv_bfloat16 h0 = __float2bfloat16(v0);
                    __nv_bfloat16 h1 = __float2bfloat16(v1);
                    __nv_bfloat16 l0 = __float2bfloat16(v0 - __bfloat162float(h0));
                    __nv_bfloat16 l1 = __float2bfloat16(v1 - __bfloat162float(h1));
                    phh[j] = (unsigned)__bfloat16_as_ushort(h0) | ((unsigned)__bfloat16_as_ushort(h1) << 16);
                    pll[j] = (unsigned)__bfloat16_as_ushort(l0) | ((unsigned)__bfloat16_as_ushort(l1) << 16);
                }
                uint4* dh = (uint4*)(g_h_hi + (size_t)slot * HIDDENV + nbase + gq * 32);
                uint4* dl = (uint4*)(g_h_lo + (size_t)slot * HIDDENV + nbase + gq * 32);
#pragma unroll
                for (int q = 0; q < 4; q++) {
                    dh[q] = make_uint4(phh[4 * q], phh[4 * q + 1], phh[4 * q + 2], phh[4 * q + 3]);
                    dl[q] = make_uint4(pll[4 * q], pll[4 * q + 1], pll[4 * q + 2], pll[4 * q + 3]);
                }
            } else {
                float* dst = out + (size_t)tok * DIMV + nbase + gq * 32;
#pragma unroll
                for (int j = 0; j < 32; j++)
                    atomicAdd(dst + j, w * __uint_as_float(r[j]));
            }
        }
    }

    TC_FENCE_BEFORE();
    __syncthreads();
    if (tid == 0) {
        asm volatile("mbarrier.inval.shared.b64 [%0];" :: "r"(sb + 8) : "memory");
        asm volatile("mbarrier.inval.shared.b64 [%0];" :: "r"(sb + 16) : "memory");
    }
    __syncthreads();
    if (wid == 0) TC_DEALLOC(tmem, TMEM_COLS);

#else
    // ============ plain-CUDA fallback (non-'a' gencode pass only) ============
    // Correct but slow; at runtime the exact-match sm_103a cubin runs instead.
    (void)wid; (void)lid;
    float* Bsh = (float*)smem;              // BN floats per k
    int m = mbase + tid;
    bool valid = (m < cnt);
    int arow = base + (valid ? m : 0);
    const __nv_bfloat16* ah = Ahi + (size_t)arow * KDIM;
    const __nv_bfloat16* al = Alo + (size_t)arow * KDIM;

    float acc[BN];
#pragma unroll
    for (int c = 0; c < BN; c++) acc[c] = 0.f;

    for (int k = 0; k < KDIM; k++) {
        __syncthreads();
        for (int c = tid; c < BN; c += 128) {
            size_t bi = ((size_t)e * NROWS + (nbase + c)) * KDIM + k;
            Bsh[c] = __bfloat162float(Bhi[bi]) + __bfloat162float(Blo[bi]);
        }
        __syncthreads();
        float a = __bfloat162float(ah[k]) + __bfloat162float(al[k]);
#pragma unroll 8
        for (int c = 0; c < BN; c++) acc[c] += a * Bsh[c];
    }

    if (valid) {
        int slot = base + m;
        if (MODE == 0) {
            __nv_bfloat16* dh = g_h_hi + (size_t)slot * HIDDENV + nbase;
            __nv_bfloat16* dl = g_h_lo + (size_t)slot * HIDDENV + nbase;
            for (int c = 0; c < BN; c++) {
                float v = fmaxf(acc[c], 0.f); v *= v;
                __nv_bfloat16 h = __float2bfloat16(v);
                dh[c] = h;
                dl[c] = __float2bfloat16(v - __bfloat162float(h));
            }
        } else {
            int   tok = g_slot_token[slot];
            float w   = g_slot_w[slot];
            float* dst = out + (size_t)tok * DIMV + nbase;
            for (int c = 0; c < BN; c++) atomicAdd(dst + c, w * acc[c]);
        }
    }
#endif
}

// ---------------- launch ----------------
extern "C" void kernel_launch(void* const* d_in, const int* in_sizes, int n_in,
                              void* d_out, int out_size) {
    const float* x   = (const float*)d_in[0];  // [1,2048,1024]
    const float* Wr  = (const float*)d_in[1];  // [8,1024]
    const float* Wfc = (const float*)d_in[2];  // [8,2048,1024]
    const float* Wpj = (const float*)d_in[3];  // [8,1024,2048]
    float* out = (float*)d_out;

    cudaFuncSetAttribute(moe_gemm_tc<DIMV, HIDDENV, 0>,
                         cudaFuncAttributeMaxDynamicSharedMemorySize, SMEM_TOTAL);
    cudaFuncSetAttribute(moe_gemm_tc<HIDDENV, DIMV, 1>,
                         cudaFuncAttributeMaxDynamicSharedMemorySize, SMEM_TOTAL);

    zero_kernel<<<(out_size + 255) / 256, 256>>>(out, out_size);
    router_kernel<<<NTOK / 4, 128>>>(x, Wr);
    build_kernel<<<1, 256>>>();

    // split weights into bf16 hi/lo (8 elems per thread)
    const int n8 = NEXP * HIDDENV * DIMV / 8;
    convert_w_kernel<0><<<n8 / 256, 256>>>(Wfc);
    convert_w_kernel<1><<<n8 / 256, 256>>>(Wpj);

    // gather + split activations per slot
    gather_x_kernel<<<NSLOT, 256>>>(x);

    // fc GEMM: [cnt x 1024] * [1024 x 2048] -> relu^2 -> g_h hi/lo
    moe_gemm_tc<DIMV, HIDDENV, 0>
        <<<dim3(HIDDENV / BN, NSLOT / BM, NEXP), 128, SMEM_TOTAL>>>(nullptr);

    // proj GEMM: [cnt x 2048] * [2048 x 1024] -> weighted accumulate -> out
    moe_gemm_tc<HIDDENV, DIMV, 1>
        <<<dim3(DIMV / BN, NSLOT / BM, NEXP), 128, SMEM_TOTAL>>>(out);
}